// round 3
// baseline (speedup 1.0000x reference)
#include <cuda_runtime.h>

#define BB 64
#define NN 512
#define EPS 1e-10f
#define L2E 1.4426950408889634f   // log2(e)

// Scratch (allocation-free rule: __device__ globals)
__device__ float4   g_items[BB * NN];   // {gain, disc, exp(score), score}
__device__ float    g_rowScale[BB];     // ln2 / (idcg * (cnt+eps)) / B
__device__ float    g_accum = 0.0f;
__device__ unsigned g_count = 0u;

// ---------------- Kernel 1: per-item precompute, per-row constants -------------
// grid (16, 64), 256 threads. Block (q,row) owns items [q*32, q*32+32):
// 8 threads per item, each scanning 64 j's via float4 LDS; shfl-8 reduce.
__global__ void lr_prep(const float* __restrict__ scores,
                        const float* __restrict__ relevance) {
    const int q   = blockIdx.x;
    const int row = blockIdx.y;
    const int t   = threadIdx.x;

    __shared__ float4 ss4[NN / 4];
    __shared__ int    counts[5];
    __shared__ float  wred[8];
    float* ss = (float*)ss4;

    ss[t]       = scores[row * NN + t];
    ss[t + 256] = scores[row * NN + t + 256];
    if (q == 0 && t < 5) counts[t] = 0;
    __syncthreads();

    // row histogram (only q==0 block)
    if (q == 0) {
        atomicAdd(&counts[(int)relevance[row * NN + t]], 1);
        atomicAdd(&counts[(int)relevance[row * NN + t + 256]], 1);
    }

    // partial predicted rank (1-based, stable tie-break by index)
    const int i_loc = t >> 3;
    const int part  = t & 7;
    const int i     = q * 32 + i_loc;
    const float si  = ss[i];
    int cnt = 0;
    const int m0 = part * 16;
    #pragma unroll 16
    for (int m = 0; m < 16; ++m) {
        float4 v = ss4[m0 + m];
        int jb = (m0 + m) * 4;
        cnt += (v.x > si) || (v.x == si && (jb + 0) < i);
        cnt += (v.y > si) || (v.y == si && (jb + 1) < i);
        cnt += (v.z > si) || (v.z == si && (jb + 2) < i);
        cnt += (v.w > si) || (v.w == si && (jb + 3) < i);
    }
    cnt += __shfl_down_sync(0xffffffffu, cnt, 4, 8);
    cnt += __shfl_down_sync(0xffffffffu, cnt, 2, 8);
    cnt += __shfl_down_sync(0xffffffffu, cnt, 1, 8);

    if (part == 0) {
        int rank = cnt + 1;
        int r = (int)relevance[row * NN + i];
        float g = (float)((1 << r) - 1);
        float d = __fdividef(1.0f, __log2f((float)(rank + 2)));
        g_items[row * NN + i] = make_float4(g, d, __expf(si), si);
    }

    // Row constants (q==0 block only; condition is block-uniform)
    if (q == 0) {
        __syncthreads();
        int c4 = counts[4], c3 = counts[3], c2 = counts[2], c1 = counts[1];
        int b4 = c4, b3 = b4 + c3, b2 = b3 + c2, b1 = b2 + c1;

        // ideal DCG: position p holds the p-th highest relevance
        float v = 0.0f;
        #pragma unroll
        for (int h = 0; h < 2; ++h) {
            int p = t + h * 256;
            float gl = p < b4 ? 15.f : p < b3 ? 7.f : p < b2 ? 3.f : p < b1 ? 1.f : 0.f;
            v += __fdividef(gl, __log2f((float)(p + 2)));
        }
        #pragma unroll
        for (int o = 16; o > 0; o >>= 1) v += __shfl_down_sync(0xffffffffu, v, o);
        if ((t & 31) == 0) wred[t >> 5] = v;
        __syncthreads();
        if (t < 32) {
            float v2 = (t < 8) ? wred[t] : 0.0f;
            #pragma unroll
            for (int o = 4; o > 0; o >>= 1) v2 += __shfl_down_sync(0xffffffffu, v2, o);
            if (t == 0) {
                float idcg = fmaxf(v2, EPS);
                int c0 = NN - (c4 + c3 + c2 + c1);
                float sq = (float)c4 * c4 + (float)c3 * c3 + (float)c2 * c2 +
                           (float)c1 * c1 + (float)c0 * c0;
                float cntf = 0.5f * ((float)NN * NN - sq);
                g_rowScale[row] = 0.6931471805599453f /
                                  (idcg * (cntf + EPS)) / (float)BB;
            }
        }
    }
}

// ---------------- Kernel 2: pairwise over unordered pairs ----------------------
// grid (8, 64), 256 threads. bx = ic + 2*kc: ic picks i-half, kc picks 64-wide
// k-chunk. j = i+k in doubled SMEM; both pair directions share one log2.
__global__ void lr_pairs(float* __restrict__ out) {
    __shared__ float4 sj[2 * NN];
    const int row = blockIdx.y;
    const int tid = threadIdx.x;

    const float4* items = g_items + row * NN;
    for (int k = tid; k < NN; k += 256) {
        float4 v = items[k];
        sj[k] = v;
        sj[k + NN] = v;
    }
    __syncthreads();

    const int ic = blockIdx.x & 1;
    const int kc = blockIdx.x >> 1;      // 0..3
    const int i  = ic * 256 + tid;
    const float4 mi = sj[i];
    const float gi = mi.x, di = mi.y, si = mi.w;
    const float Einv = __fdividef(1.0f, mi.z);   // exp(-s_i)

    const int k0 = 1 + kc * 64;
    const int k1 = (kc == 3) ? 256 : (k0 + 64);  // kc=3 covers 193..255 (+ diag)

    float acc = 0.0f;
    #pragma unroll 8
    for (int k = k0; k < k1; ++k) {
        float4 mj = sj[i + k];
        float dg  = gi - mj.x;                   // >0: i wins, <0: j wins
        float dd  = fabsf(di - mj.y);
        float u   = Einv * mj.z;                 // exp(s_j - s_i)
        float lg  = __log2f(1.0f + u);           // softplus(s_i-s_j)/ln2
        float alt = fmaf(si - mj.w, L2E, lg);    // softplus(s_j-s_i)/ln2
        float sel = (dg > 0.0f) ? lg : alt;
        acc = fmaf(fabsf(dg) * dd, sel, acc);
    }
    // distance-256 diagonal: count once (ic==0 blocks, block-uniform)
    if (kc == 3 && ic == 0) {
        float4 mj = sj[i + 256];
        float dg  = gi - mj.x;
        float dd  = fabsf(di - mj.y);
        float u   = Einv * mj.z;
        float lg  = __log2f(1.0f + u);
        float alt = fmaf(si - mj.w, L2E, lg);
        float sel = (dg > 0.0f) ? lg : alt;
        acc = fmaf(fabsf(dg) * dd, sel, acc);
    }

    // block reduce (8 warps)
    #pragma unroll
    for (int o = 16; o > 0; o >>= 1) acc += __shfl_down_sync(0xffffffffu, acc, o);
    __shared__ float ws[8];
    if ((tid & 31) == 0) ws[tid >> 5] = acc;
    __syncthreads();
    if (tid < 32) {
        float bs = (tid < 8) ? ws[tid] : 0.0f;
        #pragma unroll
        for (int o = 4; o > 0; o >>= 1) bs += __shfl_down_sync(0xffffffffu, bs, o);
        if (tid == 0) {
            atomicAdd(&g_accum, bs * g_rowScale[row]);
            __threadfence();
            unsigned n = atomicAdd(&g_count, 1u);
            if (n == 8u * BB - 1u) {             // last block finalizes
                float total = atomicAdd(&g_accum, 0.0f);
                out[0] = total;
                g_accum = 0.0f;                  // reset for next graph replay
                g_count = 0u;
            }
        }
    }
}

extern "C" void kernel_launch(void* const* d_in, const int* in_sizes, int n_in,
                              void* d_out, int out_size) {
    const float* scores    = (const float*)d_in[0];
    const float* relevance = (const float*)d_in[1];
    float* out = (float*)d_out;

    lr_prep<<<dim3(16, BB), 256>>>(scores, relevance);
    lr_pairs<<<dim3(8, BB), 256>>>(out);
}

// round 4
// speedup vs baseline: 1.4355x; 1.4355x over previous
#include <cuda_runtime.h>

#define BB 64
#define NN 512
#define EPS 1e-10f

// Scratch (allocation-free rule: __device__ globals)
// Items stored at RELEVANCE-SORTED positions: {gain, disc, exp(score), lo_as_int}
// lo = first sorted position whose relevance is strictly lower than this item's.
__device__ float4   g_items[BB * NN];
__device__ float    g_rowScale[BB];     // ln2 / (idcg * (cnt+eps)) / B
__device__ float    g_accum = 0.0f;
__device__ unsigned g_count = 0u;

// ---------------- Kernel 1: ranks + sorted placement + row constants -----------
// grid (4, 64), 128 threads. Block q owns items [q*128, q*128+128).
// Broadcast SMEM scans (j uniform across warp) -> conflict-free.
__global__ void lr_prep(const float* __restrict__ scores,
                        const float* __restrict__ relevance) {
    const int q   = blockIdx.x;
    const int row = blockIdx.y;
    const int t   = threadIdx.x;

    __shared__ float ss[NN];
    __shared__ int   rr[NN];
    __shared__ int   counts[5];
    __shared__ float wred[4];

    if (t < 5) counts[t] = 0;
    #pragma unroll
    for (int k = t; k < NN; k += 128) {
        ss[k] = scores[row * NN + k];
        rr[k] = (int)relevance[row * NN + k];
    }
    __syncthreads();

    // per-block histogram (every block needs the counts)
    #pragma unroll
    for (int k = t; k < NN; k += 128) atomicAdd(&counts[rr[k]], 1);

    // single scan: score-rank count + same-rel-lower-index count
    const int i  = q * 128 + t;
    const float si = ss[i];
    const int   ri = rr[i];
    int rkcnt = 0, same = 0;
    #pragma unroll 8
    for (int j = 0; j < NN; ++j) {
        float sj  = ss[j];
        bool  jlt = j < i;
        rkcnt += (sj > si) || (sj == si && jlt);
        same  += (rr[j] == ri) && jlt;
    }
    __syncthreads();  // counts complete

    const int c4 = counts[4], c3 = counts[3], c2 = counts[2], c1 = counts[1];
    // base[r] = number of items with relevance > r
    int base = (ri == 4) ? 0
             : (ri == 3) ? c4
             : (ri == 2) ? c4 + c3
             : (ri == 1) ? c4 + c3 + c2
                         : c4 + c3 + c2 + c1;
    int cr = (ri == 4) ? c4 : (ri == 3) ? c3 : (ri == 2) ? c2
           : (ri == 1) ? c1 : (NN - (c4 + c3 + c2 + c1));
    int pos = base + same;
    int lo  = base + cr;                       // start of strictly-lower region

    float g = (float)((1 << ri) - 1);
    float d = __fdividef(1.0f, __log2f((float)(rkcnt + 3)));  // rank = rkcnt+1
    g_items[row * NN + pos] = make_float4(g, d, __expf(si), __int_as_float(lo));

    // Row constants (q==0 block only; block-uniform branch)
    if (q == 0) {
        int b4 = c4, b3 = b4 + c3, b2 = b3 + c2, b1 = b2 + c1;
        float v = 0.0f;
        #pragma unroll
        for (int h = 0; h < 4; ++h) {
            int p = t + h * 128;
            float gl = p < b4 ? 15.f : p < b3 ? 7.f : p < b2 ? 3.f : p < b1 ? 1.f : 0.f;
            v += __fdividef(gl, __log2f((float)(p + 2)));
        }
        #pragma unroll
        for (int o = 16; o > 0; o >>= 1) v += __shfl_down_sync(0xffffffffu, v, o);
        if ((t & 31) == 0) wred[t >> 5] = v;
        __syncthreads();
        if (t == 0) {
            float idcg = fmaxf(wred[0] + wred[1] + wred[2] + wred[3], EPS);
            int c0 = NN - (c4 + c3 + c2 + c1);
            float sq = (float)c4 * c4 + (float)c3 * c3 + (float)c2 * c2 +
                       (float)c1 * c1 + (float)c0 * c0;
            float cntf = 0.5f * ((float)NN * NN - sq);
            g_rowScale[row] = 0.6931471805599453f /
                              (idcg * (cntf + EPS)) / (float)BB;
        }
    }
}

// ---------------- Kernel 2: valid pairs only (rel-sorted) ----------------------
// grid (8, 64), 256 threads. Thread owns sorted positions t and 511-t (balanced).
// Item at p pairs with j in [lo_p, 512): all pairs valid, dg > 0 guaranteed.
// Block c handles congruence class j % 8 == c -> equal work per block.
__global__ void lr_pairs(float* __restrict__ out) {
    __shared__ float4 sj[NN];
    const int row = blockIdx.y;
    const int c   = blockIdx.x;      // 0..7
    const int t   = threadIdx.x;

    const float4* items = g_items + row * NN;
    sj[t]       = items[t];
    sj[t + 256] = items[t + 256];
    __syncthreads();

    float acc = 0.0f;
    #pragma unroll
    for (int item = 0; item < 2; ++item) {
        const int p = item ? (NN - 1 - t) : t;
        const float4 mi = sj[p];
        const int lo = __float_as_int(mi.w);
        if (lo < NN) {
            const float gi = mi.x, di = mi.y;
            const float Einv = __fdividef(1.0f, mi.z);      // exp(-s_i)
            int js = lo + ((c - lo) & 7);                   // first j>=lo, j%8==c
            #pragma unroll 4
            for (int j = js; j < NN; j += 8) {
                float4 mj = sj[j];
                float w = (gi - mj.x) * fabsf(di - mj.y);   // dg > 0 by construction
                float u = Einv * mj.z;                      // exp(s_j - s_i)
                acc = fmaf(w, __log2f(1.0f + u), acc);      // ln2 folded in rowScale
            }
        }
    }

    // block reduce (8 warps)
    #pragma unroll
    for (int o = 16; o > 0; o >>= 1) acc += __shfl_down_sync(0xffffffffu, acc, o);
    __shared__ float ws[8];
    if ((t & 31) == 0) ws[t >> 5] = acc;
    __syncthreads();
    if (t < 32) {
        float bs = (t < 8) ? ws[t] : 0.0f;
        #pragma unroll
        for (int o = 4; o > 0; o >>= 1) bs += __shfl_down_sync(0xffffffffu, bs, o);
        if (t == 0) {
            atomicAdd(&g_accum, bs * g_rowScale[row]);
            __threadfence();
            unsigned n = atomicAdd(&g_count, 1u);
            if (n == 8u * BB - 1u) {             // last block finalizes
                float total = atomicAdd(&g_accum, 0.0f);
                out[0] = total;
                g_accum = 0.0f;                  // reset for next graph replay
                g_count = 0u;
            }
        }
    }
}

extern "C" void kernel_launch(void* const* d_in, const int* in_sizes, int n_in,
                              void* d_out, int out_size) {
    const float* scores    = (const float*)d_in[0];
    const float* relevance = (const float*)d_in[1];
    float* out = (float*)d_out;

    lr_prep<<<dim3(4, BB), 128>>>(scores, relevance);
    lr_pairs<<<dim3(8, BB), 256>>>(out);
}

// round 5
// speedup vs baseline: 1.6691x; 1.1627x over previous
#include <cuda_runtime.h>

#define BB 64
#define NN 512
#define EPS 1e-10f

// Scratch (allocation-free rule: __device__ globals)
// Items at RELEVANCE-SORTED positions: {gain, disc, exp(score), lo_as_int}
// lo = first sorted position with strictly lower relevance.
__device__ float4   g_items[BB * NN];
__device__ float    g_rowScale[BB];     // ln2 / (idcg * (cnt+eps)) / B
__device__ float    g_accum = 0.0f;
__device__ unsigned g_count = 0u;

// ---------------- Kernel 1: ranks + sorted placement + row constants -----------
// grid (8, 64), 256 threads. Block q owns items [q*64, q*64+64).
// 4 threads/item, j = 4*jj + part (adjacent float2 addrs -> conflict-free).
// Tie-break (j < i) handled by loop split: no runtime index compares.
__global__ void lr_prep(const float* __restrict__ scores,
                        const float* __restrict__ relevance) {
    const int q   = blockIdx.x;
    const int row = blockIdx.y;
    const int t   = threadIdx.x;

    __shared__ float2 sv[NN];           // {score, rel}
    __shared__ int    counts[5];
    __shared__ float  wred[8];

    if (t < 5) counts[t] = 0;
    sv[t]       = make_float2(scores[row * NN + t],       relevance[row * NN + t]);
    sv[t + 256] = make_float2(scores[row * NN + t + 256], relevance[row * NN + t + 256]);
    __syncthreads();

    // per-block histogram (latency hidden behind the scan below)
    atomicAdd(&counts[(int)sv[t].y], 1);
    atomicAdd(&counts[(int)sv[t + 256].y], 1);

    const int   i    = q * 64 + (t >> 2);
    const int   part = t & 3;
    const float si   = sv[i].x;
    const float rif  = sv[i].y;
    const int   thr  = (i - part + 3) >> 2;   // #jj with j = 4jj+part < i

    int rk = 0, same = 0;
    int jj = 0;
    #pragma unroll 8
    for (; jj < thr; ++jj) {                  // region j < i
        float2 v = sv[4 * jj + part];
        rk   += (v.x >= si);                  // (x>si) || (x==si && j<i)
        same += (v.y == rif);
    }
    #pragma unroll 8
    for (; jj < 128; ++jj) {                  // region j >= i (incl. self)
        float2 v = sv[4 * jj + part];
        rk += (v.x > si);
    }

    // pack & quad-reduce (rk<=512, same<=512: no cross-field carry)
    int pk = rk | (same << 16);
    pk += __shfl_down_sync(0xffffffffu, pk, 2, 4);
    pk += __shfl_down_sync(0xffffffffu, pk, 1, 4);

    __syncthreads();                          // counts complete
    const int c4 = counts[4], c3 = counts[3], c2 = counts[2], c1 = counts[1];

    if (part == 0) {
        int rkT   = pk & 0xffff;              // # items ranked better
        int sameT = pk >> 16;                 // # same-rel items with j<i
        int r = (int)rif;
        int base = (r == 4) ? 0
                 : (r == 3) ? c4
                 : (r == 2) ? c4 + c3
                 : (r == 1) ? c4 + c3 + c2
                            : c4 + c3 + c2 + c1;
        int cr = (r == 4) ? c4 : (r == 3) ? c3 : (r == 2) ? c2
               : (r == 1) ? c1 : (NN - (c4 + c3 + c2 + c1));
        float g = (float)((1 << r) - 1);
        float d = __fdividef(1.0f, __log2f((float)(rkT + 3)));  // rank = rkT+1
        g_items[row * NN + base + sameT] =
            make_float4(g, d, __expf(si), __int_as_float(base + cr));
    }

    // Row constants (q==0 only; block-uniform branch so syncs are legal)
    if (q == 0) {
        int b4 = c4, b3 = b4 + c3, b2 = b3 + c2, b1 = b2 + c1;
        float v = 0.0f;
        #pragma unroll
        for (int h = 0; h < 2; ++h) {
            int p = t + h * 256;
            float gl = p < b4 ? 15.f : p < b3 ? 7.f : p < b2 ? 3.f : p < b1 ? 1.f : 0.f;
            v += __fdividef(gl, __log2f((float)(p + 2)));
        }
        #pragma unroll
        for (int o = 16; o > 0; o >>= 1) v += __shfl_down_sync(0xffffffffu, v, o);
        if ((t & 31) == 0) wred[t >> 5] = v;
        __syncthreads();
        if (t == 0) {
            float idcg = fmaxf(wred[0] + wred[1] + wred[2] + wred[3] +
                               wred[4] + wred[5] + wred[6] + wred[7], EPS);
            int c0 = NN - (c4 + c3 + c2 + c1);
            float sq = (float)c4 * c4 + (float)c3 * c3 + (float)c2 * c2 +
                       (float)c1 * c1 + (float)c0 * c0;
            float cntf = 0.5f * ((float)NN * NN - sq);
            g_rowScale[row] = 0.6931471805599453f /
                              (idcg * (cntf + EPS)) / (float)BB;
        }
    }
}

// ---------------- Kernel 2: valid pairs only (rel-sorted) ----------------------
// grid (8, 64), 256 threads. Thread owns positions t and 511-t (balanced: work
// sum ~ const). Block c takes the c-th eighth of EACH thread's contiguous range
// [lo, 512) -> contiguous per-thread j, scattered across warp (conflict-free).
__global__ void lr_pairs(float* __restrict__ out) {
    __shared__ float4 sj[NN];
    const int row = blockIdx.y;
    const int c   = blockIdx.x;      // 0..7
    const int t   = threadIdx.x;

    const float4* items = g_items + row * NN;
    sj[t]       = items[t];
    sj[t + 256] = items[t + 256];
    __syncthreads();

    float acc0 = 0.0f, acc1 = 0.0f;

    {   // item A: position t
        const float4 mi = sj[t];
        const int lo  = __float_as_int(mi.w);
        const int len = NN - lo;
        const int j0 = lo + ((c * len) >> 3);
        const int j1 = lo + (((c + 1) * len) >> 3);
        const float gi = mi.x, di = mi.y;
        const float Einv = __fdividef(1.0f, mi.z);
        #pragma unroll 4
        for (int j = j0; j < j1; ++j) {
            float4 mj = sj[j];
            float w = (gi - mj.x) * fabsf(di - mj.y);   // dg>0 by construction
            float u = Einv * mj.z;                      // exp(s_j - s_i)
            acc0 = fmaf(w, __log2f(1.0f + u), acc0);    // ln2 folded in rowScale
        }
    }
    {   // item B: position 511 - t
        const float4 mi = sj[NN - 1 - t];
        const int lo  = __float_as_int(mi.w);
        const int len = NN - lo;
        const int j0 = lo + ((c * len) >> 3);
        const int j1 = lo + (((c + 1) * len) >> 3);
        const float gi = mi.x, di = mi.y;
        const float Einv = __fdividef(1.0f, mi.z);
        #pragma unroll 4
        for (int j = j0; j < j1; ++j) {
            float4 mj = sj[j];
            float w = (gi - mj.x) * fabsf(di - mj.y);
            float u = Einv * mj.z;
            acc1 = fmaf(w, __log2f(1.0f + u), acc1);
        }
    }
    float acc = acc0 + acc1;

    // block reduce (8 warps)
    #pragma unroll
    for (int o = 16; o > 0; o >>= 1) acc += __shfl_down_sync(0xffffffffu, acc, o);
    __shared__ float ws[8];
    if ((t & 31) == 0) ws[t >> 5] = acc;
    __syncthreads();
    if (t < 32) {
        float bs = (t < 8) ? ws[t] : 0.0f;
        #pragma unroll
        for (int o = 4; o > 0; o >>= 1) bs += __shfl_down_sync(0xffffffffu, bs, o);
        if (t == 0) {
            atomicAdd(&g_accum, bs * g_rowScale[row]);
            __threadfence();
            unsigned n = atomicAdd(&g_count, 1u);
            if (n == 8u * BB - 1u) {             // last block finalizes
                float total = atomicAdd(&g_accum, 0.0f);
                out[0] = total;
                g_accum = 0.0f;                  // reset for next graph replay
                g_count = 0u;
            }
        }
    }
}

extern "C" void kernel_launch(void* const* d_in, const int* in_sizes, int n_in,
                              void* d_out, int out_size) {
    const float* scores    = (const float*)d_in[0];
    const float* relevance = (const float*)d_in[1];
    float* out = (float*)d_out;

    lr_prep<<<dim3(8, BB), 256>>>(scores, relevance);
    lr_pairs<<<dim3(8, BB), 256>>>(out);
}